// round 15
// baseline (speedup 1.0000x reference)
#include <cuda_runtime.h>
#include <cuda_bf16.h>
#include <math.h>
#include <stdint.h>

// Problem constants
#define B_  64
#define T_  512
#define D_  512
#define H_  1024
#define G4  4096   // 4*H

// ---------------------------------------------------------------------------
// Device globals (allocation-free scratch)
// ---------------------------------------------------------------------------
__device__ float g_xw[(size_t)B_ * T_ * G4];          // [B*T, 4H] input proj
__device__ __nv_bfloat16 g_uthi[(size_t)G4 * H_];     // U^T hi [4096][1024]
__device__ __nv_bfloat16 g_utlo[(size_t)G4 * H_];     // U^T lo
__device__ __nv_bfloat16 g_wthi[(size_t)G4 * D_];     // W^T hi [4096][512]
__device__ __nv_bfloat16 g_wtlo[(size_t)G4 * D_];     // W^T lo
__device__ __nv_bfloat16 g_xhi[(size_t)B_ * T_ * D_]; // x hi [32768][512]
__device__ __nv_bfloat16 g_xlo[(size_t)B_ * T_ * D_]; // x lo
__device__ __nv_bfloat16 g_hh[2][B_ * H_];            // h hi, ping-pong by t
__device__ __nv_bfloat16 g_hl[2][B_ * H_];            // h lo, ping-pong by t
__device__ float g_c[B_ * H_];                        // cell state
__device__ float g_part[4][64][B_ * 64];              // split-K partials
__device__ int   g_sem[64];                           // per-tile arrival sem

// ---------------------------------------------------------------------------
// PTX wrappers (proven)
// ---------------------------------------------------------------------------
__device__ __forceinline__ void ldsm4(uint32_t& r0, uint32_t& r1,
                                      uint32_t& r2, uint32_t& r3,
                                      uint32_t addr) {
    asm volatile(
        "ldmatrix.sync.aligned.m8n8.x4.shared.b16 {%0,%1,%2,%3}, [%4];"
        : "=r"(r0), "=r"(r1), "=r"(r2), "=r"(r3)
        : "r"(addr));
}

__device__ __forceinline__ void mma_bf16(float* ac, const uint32_t* a,
                                         uint32_t b0, uint32_t b1) {
    asm volatile(
        "mma.sync.aligned.m16n8k16.row.col.f32.bf16.bf16.f32 "
        "{%0,%1,%2,%3}, {%4,%5,%6,%7}, {%8,%9}, {%0,%1,%2,%3};"
        : "+f"(ac[0]), "+f"(ac[1]), "+f"(ac[2]), "+f"(ac[3])
        : "r"(a[0]), "r"(a[1]), "r"(a[2]), "r"(a[3]), "r"(b0), "r"(b1));
}

__device__ __forceinline__ float sigmoidf_(float x) {
    return 1.0f / (1.0f + expf(-x));
}

// ---------------------------------------------------------------------------
// Init: zero h0 (both ping-pong buffers, both splits), c0, semaphores.
// ---------------------------------------------------------------------------
__global__ void init_state_kernel() {
    int i = blockIdx.x * blockDim.x + threadIdx.x;
    if (i < B_ * H_) {
        __nv_bfloat16 z = __float2bfloat16(0.0f);
        g_hh[0][i] = z; g_hh[1][i] = z;
        g_hl[0][i] = z; g_hl[1][i] = z;
        g_c[i] = 0.0f;
    }
    if (i < 64) g_sem[i] = 0;
}

// ---------------------------------------------------------------------------
// Transpose + bf16 hi/lo split for U: [1024][4096] -> U^T [4096][1024]
// ---------------------------------------------------------------------------
__global__ __launch_bounds__(256) void split_u_kernel(const float* __restrict__ U) {
    __shared__ float tile[32][33];
    const int k0 = blockIdx.x * 32;
    const int n0 = blockIdx.y * 32;
    const int tid = threadIdx.x;
    #pragma unroll
    for (int i = 0; i < 4; ++i) {
        int idx = tid + 256 * i;
        int kl = idx >> 5, nl = idx & 31;
        tile[kl][nl] = U[(size_t)(k0 + kl) * G4 + n0 + nl];
    }
    __syncthreads();
    #pragma unroll
    for (int i = 0; i < 4; ++i) {
        int idx = tid + 256 * i;
        int nl = idx >> 5, kl = idx & 31;
        float v = tile[kl][nl];
        __nv_bfloat16 hi = __float2bfloat16(v);
        __nv_bfloat16 lo = __float2bfloat16(v - __bfloat162float(hi));
        size_t dst = (size_t)(n0 + nl) * H_ + k0 + kl;
        g_uthi[dst] = hi;
        g_utlo[dst] = lo;
    }
}

// ---------------------------------------------------------------------------
// Same for W: [512][4096] -> W^T [4096][512]
// ---------------------------------------------------------------------------
__global__ __launch_bounds__(256) void split_w_kernel(const float* __restrict__ W) {
    __shared__ float tile[32][33];
    const int k0 = blockIdx.x * 32;
    const int n0 = blockIdx.y * 32;
    const int tid = threadIdx.x;
    #pragma unroll
    for (int i = 0; i < 4; ++i) {
        int idx = tid + 256 * i;
        int kl = idx >> 5, nl = idx & 31;
        tile[kl][nl] = W[(size_t)(k0 + kl) * G4 + n0 + nl];
    }
    __syncthreads();
    #pragma unroll
    for (int i = 0; i < 4; ++i) {
        int idx = tid + 256 * i;
        int nl = idx >> 5, kl = idx & 31;
        float v = tile[kl][nl];
        __nv_bfloat16 hi = __float2bfloat16(v);
        __nv_bfloat16 lo = __float2bfloat16(v - __bfloat162float(hi));
        size_t dst = (size_t)(n0 + nl) * D_ + k0 + kl;
        g_wthi[dst] = hi;
        g_wtlo[dst] = lo;
    }
}

// ---------------------------------------------------------------------------
// Elementwise bf16 hi/lo split of x, vectorized (float4 reads)
// ---------------------------------------------------------------------------
__global__ __launch_bounds__(256) void split_x_kernel(
        const float* __restrict__ x, int n4) {
    int i = blockIdx.x * blockDim.x + threadIdx.x;
    if (i < n4) {
        float4 v = reinterpret_cast<const float4*>(x)[i];
        __nv_bfloat16 h0 = __float2bfloat16(v.x);
        __nv_bfloat16 h1 = __float2bfloat16(v.y);
        __nv_bfloat16 h2 = __float2bfloat16(v.z);
        __nv_bfloat16 h3 = __float2bfloat16(v.w);
        __nv_bfloat162 hi01; hi01.x = h0; hi01.y = h1;
        __nv_bfloat162 hi23; hi23.x = h2; hi23.y = h3;
        __nv_bfloat162 lo01;
        lo01.x = __float2bfloat16(v.x - __bfloat162float(h0));
        lo01.y = __float2bfloat16(v.y - __bfloat162float(h1));
        __nv_bfloat162 lo23;
        lo23.x = __float2bfloat16(v.z - __bfloat162float(h2));
        lo23.y = __float2bfloat16(v.w - __bfloat162float(h3));
        *reinterpret_cast<__nv_bfloat162*>(&g_xhi[i * 4]) = hi01;
        *reinterpret_cast<__nv_bfloat162*>(&g_xhi[i * 4 + 2]) = hi23;
        *reinterpret_cast<__nv_bfloat162*>(&g_xlo[i * 4]) = lo01;
        *reinterpret_cast<__nv_bfloat162*>(&g_xlo[i * 4 + 2]) = lo23;
    }
}

// ---------------------------------------------------------------------------
// Phase 1 on tensor cores (ROUND-12 VERBATIM — proven, no spill).
// BM=64 x BN=64, synchronous smem fill, register-scoped 3-pass product.
// ---------------------------------------------------------------------------
#define G1_STR 72
__global__ __launch_bounds__(256) void gemm1_mma_kernel(
        const float* __restrict__ bias) {
    __shared__ __align__(16) __nv_bfloat16 Ahs[64][G1_STR];
    __shared__ __align__(16) __nv_bfloat16 Als[64][G1_STR];
    __shared__ __align__(16) __nv_bfloat16 Bhs[64][G1_STR];
    __shared__ __align__(16) __nv_bfloat16 Bls[64][G1_STR];

    const int tid = threadIdx.x;
    const int bn = blockIdx.x * 64;
    const int bm = blockIdx.y * 64;

    const __nv_bfloat16* xh = g_xhi + (size_t)bm * D_;
    const __nv_bfloat16* xl = g_xlo + (size_t)bm * D_;
    const __nv_bfloat16* wh = g_wthi + (size_t)bn * D_;
    const __nv_bfloat16* wl = g_wtlo + (size_t)bn * D_;

    const int wid = tid >> 5, lane = tid & 31;
    const int m0 = (wid >> 1) * 16;
    const int nwb = (wid & 1) * 32;
    const int gid = lane >> 2, tig = lane & 3;

    const int rowA = m0 + (lane & 15);
    const int kofsA = (lane >> 4) * 8;
    const uint32_t aAh = (uint32_t)__cvta_generic_to_shared(&Ahs[0][0])
        + (uint32_t)(rowA * G1_STR + kofsA) * 2u;
    const uint32_t aAl = (uint32_t)__cvta_generic_to_shared(&Als[0][0])
        + (uint32_t)(rowA * G1_STR + kofsA) * 2u;

    const int rowBb = (lane & 7) + ((lane >> 4) << 3);
    const int kofsB = ((lane >> 3) & 1) * 8;
    const uint32_t aBh0 = (uint32_t)__cvta_generic_to_shared(&Bhs[0][0])
        + (uint32_t)((nwb + rowBb) * G1_STR + kofsB) * 2u;
    const uint32_t aBh1 = aBh0 + 16u * G1_STR * 2u;
    const uint32_t aBl0 = (uint32_t)__cvta_generic_to_shared(&Bls[0][0])
        + (uint32_t)((nwb + rowBb) * G1_STR + kofsB) * 2u;
    const uint32_t aBl1 = aBl0 + 16u * G1_STR * 2u;

    float acc[4][4] = {};

    for (int kc = 0; kc < 8; ++kc) {
        const int k0 = kc * 64;
        #pragma unroll
        for (int i = 0; i < 2; ++i) {
            int slot = tid + 256 * i;
            int row = slot >> 3, j = slot & 7;
            *reinterpret_cast<uint4*>(&Ahs[row][j * 8]) =
                *reinterpret_cast<const uint4*>(&xh[(size_t)row * D_ + k0 + j * 8]);
            *reinterpret_cast<uint4*>(&Als[row][j * 8]) =
                *reinterpret_cast<const uint4*>(&xl[(size_t)row * D_ + k0 + j * 8]);
            *reinterpret_cast<uint4*>(&Bhs[row][j * 8]) =
                *reinterpret_cast<const uint4*>(&wh[(size_t)row * D_ + k0 + j * 8]);
            *reinterpret_cast<uint4*>(&Bls[row][j * 8]) =
                *reinterpret_cast<const uint4*>(&wl[(size_t)row * D_ + k0 + j * 8]);
        }
        __syncthreads();
        #pragma unroll
        for (int s = 0; s < 4; ++s) {
            const uint32_t kk = (uint32_t)(s * 16) * 2u;
            {   // hi * hi
                uint32_t a[4], b0[4], b1[4];
                ldsm4(a[0], a[1], a[2], a[3], aAh + kk);
                ldsm4(b0[0], b0[1], b0[2], b0[3], aBh0 + kk);
                ldsm4(b1[0], b1[1], b1[2], b1[3], aBh1 + kk);
                mma_bf16(acc[0], a, b0[0], b0[1]);
                mma_bf16(acc[1], a, b0[2], b0[3]);
                mma_bf16(acc[2], a, b1[0], b1[1]);
                mma_bf16(acc[3], a, b1[2], b1[3]);
            }
            {   // hi * lo
                uint32_t a[4], b0[4], b1[4];
                ldsm4(a[0], a[1], a[2], a[3], aAh + kk);
                ldsm4(b0[0], b0[1], b0[2], b0[3], aBl0 + kk);
                ldsm4(b1[0], b1[1], b1[2], b1[3], aBl1 + kk);
                mma_bf16(acc[0], a, b0[0], b0[1]);
                mma_bf16(acc[1], a, b0[2], b0[3]);
                mma_bf16(acc[2], a, b1[0], b1[1]);
                mma_bf16(acc[3], a, b1[2], b1[3]);
            }
            {   // lo * hi
                uint32_t a[4], b0[4], b1[4];
                ldsm4(a[0], a[1], a[2], a[3], aAl + kk);
                ldsm4(b0[0], b0[1], b0[2], b0[3], aBh0 + kk);
                ldsm4(b1[0], b1[1], b1[2], b1[3], aBh1 + kk);
                mma_bf16(acc[0], a, b0[0], b0[1]);
                mma_bf16(acc[1], a, b0[2], b0[3]);
                mma_bf16(acc[2], a, b1[0], b1[1]);
                mma_bf16(acc[3], a, b1[2], b1[3]);
            }
        }
        __syncthreads();
    }

    #pragma unroll
    for (int nf = 0; nf < 4; ++nf) {
        int col = bn + nwb + nf * 8 + 2 * tig;
        float b0 = bias[col], b1 = bias[col + 1];
        size_t r0 = (size_t)(bm + m0 + gid) * G4 + col;
        size_t r1 = (size_t)(bm + m0 + gid + 8) * G4 + col;
        *reinterpret_cast<float2*>(&g_xw[r0]) =
            make_float2(acc[nf][0] + b0, acc[nf][1] + b1);
        *reinterpret_cast<float2*>(&g_xw[r1]) =
            make_float2(acc[nf][2] + b0, acc[nf][3] + b1);
    }
}

// ---------------------------------------------------------------------------
// Fused LSTM step, split-K 4. Grid 256 = 64 tiles x 4 K-quarters.
// Per CTA: A = h (64 x 256, hi/lo) resident smem (64KB); B = U^T streamed in
// 8 tiles of BK=32. Register-SCOPED mma passes (anti-spill; target <=128 regs
// so 2 CTAs/SM co-schedule). h ping-pongs by t (race-free for any wave count).
// Last of 4 arrivers per tile reduces partials + xW + pointwise.
// ---------------------------------------------------------------------------
#define KZ_ 4
#define KP_ 256                       // K per partition
#define A_STRIDE 264                  // 256 + 8 pad (bf16 elems)
#define B_STRIDE 40                   // 32 + 8 pad
#define OFF_AHI 0                     // 64*264*2 = 33792
#define OFF_ALO 33792
#define OFF_BHI 67584                 // 64*40*2 = 5120
#define OFF_BLO 72704
#define OFF_GS  77824                 // 64*66*4 = 16896
#define SMEM_P  94720

__global__ __launch_bounds__(256, 1) void lstm_step_mma(
        int t, float* __restrict__ final_out) {
    extern __shared__ char smem[];
    __nv_bfloat16* Ahi = (__nv_bfloat16*)(smem + OFF_AHI);
    __nv_bfloat16* Alo = (__nv_bfloat16*)(smem + OFF_ALO);
    __nv_bfloat16* Bhi = (__nv_bfloat16*)(smem + OFF_BHI);
    __nv_bfloat16* Blo = (__nv_bfloat16*)(smem + OFF_BLO);
    float* Gsf = (float*)(smem + OFF_GS);
    __shared__ int s_old;

    const int tid = threadIdx.x;
    const int tile = blockIdx.x >> 2;        // 0..63 column tile
    const int kz = blockIdx.x & 3;           // K quarter
    const int n0 = tile * 16;                // hidden-unit base

    const __nv_bfloat16* hin_h = g_hh[t & 1] + kz * KP_;
    const __nv_bfloat16* hin_l = g_hl[t & 1] + kz * KP_;

    // ---- Load resident A (h hi/lo, this CTA's K quarter): 64 x 256 ----
    #pragma unroll
    for (int i = 0; i < 8; ++i) {
        int slot = tid + 256 * i;            // 0..2047
        int row = slot >> 5;                 // 0..63
        int j = slot & 31;                   // 8-elem k-group
        *reinterpret_cast<uint4*>(&Ahi[row * A_STRIDE + j * 8]) =
            *reinterpret_cast<const uint4*>(&hin_h[row * H_ + j * 8]);
        *reinterpret_cast<uint4*>(&Alo[row * A_STRIDE + j * 8]) =
            *reinterpret_cast<const uint4*>(&hin_l[row * H_ + j * 8]);
    }

    // ---- B stream setup: thread -> (gate-col cc, 16B k-group kg) ----
    const int cc = tid >> 2;                 // 0..63
    const int kg = tid & 3;                  // 0..3
    const int colg = (cc >> 4) * H_ + n0 + (cc & 15);
    const __nv_bfloat16* ubh = g_uthi + (size_t)colg * H_ + kz * KP_;
    const __nv_bfloat16* ubl = g_utlo + (size_t)colg * H_ + kz * KP_;
    uint4 ph = *reinterpret_cast<const uint4*>(&ubh[kg * 8]);
    uint4 pl = *reinterpret_cast<const uint4*>(&ubl[kg * 8]);

    // ---- Warp / fragment addressing ----
    const int wid = tid >> 5, lane = tid & 31;
    const int m0 = (wid >> 1) * 16;
    const int nwb = (wid & 1) * 32;
    const int gid = lane >> 2, tig = lane & 3;

    const int rowA = m0 + (lane & 15);
    const int kofsA = (lane >> 4) * 8;
    const uint32_t aAhi = (uint32_t)__cvta_generic_to_shared(Ahi)
                          + (uint32_t)(rowA * A_STRIDE + kofsA) * 2u;
    const uint32_t aAlo = (uint32_t)__cvta_generic_to_shared(Alo)
                          + (uint32_t)(rowA * A_STRIDE + kofsA) * 2u;

    const int rowBb = (lane & 7) + ((lane >> 4) << 3);
    const int kofsB = ((lane >> 3) & 1) * 8;
    const uint32_t aBhi0 = (uint32_t)__cvta_generic_to_shared(Bhi)
                           + (uint32_t)((nwb + rowBb) * B_STRIDE + kofsB) * 2u;
    const uint32_t aBhi1 = aBhi0 + 16u * B_STRIDE * 2u;
    const uint32_t aBlo0 = (uint32_t)__cvta_generic_to_shared(Blo)
                           + (uint32_t)((nwb + rowBb) * B_STRIDE + kofsB) * 2u;
    const uint32_t aBlo1 = aBlo0 + 16u * B_STRIDE * 2u;

    float acc[4][4] = {};

    // ---- Main loop: 8 B-tiles of BK=32 over this CTA's K quarter ----
    for (int kt = 0; kt < 8; ++kt) {
        *reinterpret_cast<uint4*>(&Bhi[cc * B_STRIDE + kg * 8]) = ph;
        *reinterpret_cast<uint4*>(&Blo[cc * B_STRIDE + kg * 8]) = pl;
        __syncthreads();
        if (kt + 1 < 8) {
            ph = *reinterpret_cast<const uint4*>(&ubh[(kt + 1) * 32 + kg * 8]);
            pl = *reinterpret_cast<const uint4*>(&ubl[(kt + 1) * 32 + kg * 8]);
        }
        #pragma unroll
        for (int ch = 0; ch < 2; ++ch) {
            const uint32_t kcA = (uint32_t)(kt * 32 + ch * 16) * 2u;
            const uint32_t kcB = (uint32_t)(ch * 16) * 2u;
            {   // A-hi passes (hi*hi then hi*lo)
                uint32_t a[4];
                ldsm4(a[0], a[1], a[2], a[3], aAhi + kcA);
                {
                    uint32_t b0[4], b1[4];
                    ldsm4(b0[0], b0[1], b0[2], b0[3], aBhi0 + kcB);
                    ldsm4(b1[0], b1[1], b1[2], b1[3], aBhi1 + kcB);
                    mma_bf16(acc[0], a, b0[0], b0[1]);
                    mma_bf16(acc[1], a, b0[2], b0[3]);
                    mma_bf16(acc[2], a, b1[0], b1[1]);
                    mma_bf16(acc[3], a, b1[2], b1[3]);
                }
                {
                    uint32_t b0[4], b1[4];
                    ldsm4(b0[0], b0[1], b0[2], b0[3], aBlo0 + kcB);
                    ldsm4(b1[0], b1[1], b1[2], b1[3], aBlo1 + kcB);
                    mma_bf16(acc[0], a, b0[0], b0[1]);
                    mma_bf16(acc[1], a, b0[2], b0[3]);
                    mma_bf16(acc[2], a, b1[0], b1[1]);
                    mma_bf16(acc[3], a, b1[2], b1[3]);
                }
            }
            {   // A-lo pass (lo*hi)
                uint32_t a[4], b0[4], b1[4];
                ldsm4(a[0], a[1], a[2], a[3], aAlo + kcA);
                ldsm4(b0[0], b0[1], b0[2], b0[3], aBhi0 + kcB);
                ldsm4(b1[0], b1[1], b1[2], b1[3], aBhi1 + kcB);
                mma_bf16(acc[0], a, b0[0], b0[1]);
                mma_bf16(acc[1], a, b0[2], b0[3]);
                mma_bf16(acc[2], a, b1[0], b1[1]);
                mma_bf16(acc[3], a, b1[2], b1[3]);
            }
        }
        __syncthreads();
    }

    // ---- Write this K-quarter's partials ----
    float* mypart = &g_part[kz][tile][0];
    #pragma unroll
    for (int nf = 0; nf < 4; ++nf) {
        int col = nwb + nf * 8 + 2 * tig;
        *reinterpret_cast<float2*>(&mypart[(m0 + gid) * 64 + col]) =
            make_float2(acc[nf][0], acc[nf][1]);
        *reinterpret_cast<float2*>(&mypart[(m0 + gid + 8) * 64 + col]) =
            make_float2(acc[nf][2], acc[nf][3]);
    }
    __threadfence();
    __syncthreads();
    if (tid == 0) s_old = atomicAdd(&g_sem[tile], 1);
    __syncthreads();
    if (s_old != KZ_ * t + (KZ_ - 1)) return;   // not the last arriver
    __threadfence();

    // ---- Last arriver: sum all 4 partials into Gs (fixed order) ----
    #pragma unroll
    for (int nf = 0; nf < 4; ++nf) {
        int col = nwb + nf * 8 + 2 * tig;
        int r0 = (m0 + gid) * 64 + col;
        int r1 = (m0 + gid + 8) * 64 + col;
        float2 s0 = make_float2(0.0f, 0.0f);
        float2 s1 = make_float2(0.0f, 0.0f);
        #pragma unroll
        for (int z = 0; z < KZ_; ++z) {
            float2 a = *reinterpret_cast<const float2*>(&g_part[z][tile][r0]);
            float2 b = *reinterpret_cast<const float2*>(&g_part[z][tile][r1]);
            s0.x += a.x; s0.y += a.y;
            s1.x += b.x; s1.y += b.y;
        }
        *reinterpret_cast<float2*>(&Gsf[(m0 + gid) * 66 + col]) = s0;
        *reinterpret_cast<float2*>(&Gsf[(m0 + gid + 8) * 66 + col]) = s1;
    }
    __syncthreads();

    // ---- Fused pointwise: 1024 (b, off) pairs / 256 threads = 4 each ----
    __nv_bfloat16* hout_h = g_hh[(t + 1) & 1];
    __nv_bfloat16* hout_l = g_hl[(t + 1) & 1];
    const bool last = (t == T_ - 1);
    #pragma unroll
    for (int i = 0; i < 4; ++i) {
        int p = tid + 256 * i;               // 0..1023
        int b = p >> 4;
        int off = p & 15;
        const float* xwrow = &g_xw[((size_t)b * T_ + t) * G4 + n0 + off];
        float gi = Gsf[b * 66 + 0 * 16 + off] + xwrow[0 * H_];
        float gf = Gsf[b * 66 + 1 * 16 + off] + xwrow[1 * H_];
        float gc = Gsf[b * 66 + 2 * 16 + off] + xwrow[2 * H_];
        float go = Gsf[b * 66 + 3 * 16 + off] + xwrow[3 * H_];
        float iv = sigmoidf_(gi);
        float fv = sigmoidf_(gf);
        float cb = tanhf(gc);
        float ov = sigmoidf_(go);
        int idx = b * H_ + n0 + off;
        float cn = fv * g_c[idx] + iv * cb;
        g_c[idx] = cn;
        float hn = ov * tanhf(cn);
        __nv_bfloat16 hb = __float2bfloat16(hn);
        hout_h[idx] = hb;
        hout_l[idx] = __float2bfloat16(hn - __bfloat162float(hb));
        if (last) final_out[idx] = hn;
    }
}

// ---------------------------------------------------------------------------
// Launch: init -> splits -> tensor-core phase-1 -> 512 split-K-4 step kernels
// ---------------------------------------------------------------------------
extern "C" void kernel_launch(void* const* d_in, const int* in_sizes, int n_in,
                              void* d_out, int out_size) {
    const float* x = (const float*)d_in[0];
    const float* W = (const float*)d_in[1];
    const float* U = (const float*)d_in[2];
    const float* b = (const float*)d_in[3];
    float* out = (float*)d_out;

    cudaFuncSetAttribute(lstm_step_mma,
                         cudaFuncAttributeMaxDynamicSharedMemorySize, SMEM_P);

    init_state_kernel<<<(B_ * H_ + 255) / 256, 256>>>();

    dim3 gu(H_ / 32, G4 / 32);               // (32, 128)
    split_u_kernel<<<gu, 256>>>(U);
    dim3 gw(D_ / 32, G4 / 32);               // (16, 128)
    split_w_kernel<<<gw, 256>>>(W);

    int n4 = (B_ * T_ * D_) / 4;
    split_x_kernel<<<(n4 + 255) / 256, 256>>>(x, n4);

    dim3 g1(G4 / 64, (B_ * T_) / 64);        // (64, 512)
    gemm1_mma_kernel<<<g1, 256>>>(b);

    for (int t = 0; t < T_; ++t) {
        lstm_step_mma<<<64 * KZ_, 256, SMEM_P>>>(t, out);
    }
}

// round 17
// speedup vs baseline: 1.0301x; 1.0301x over previous
#include <cuda_runtime.h>
#include <cuda_bf16.h>
#include <math.h>
#include <stdint.h>

// Problem constants
#define B_  64
#define T_  512
#define D_  512
#define H_  1024
#define G4  4096   // 4*H

// ---------------------------------------------------------------------------
// Device globals (allocation-free scratch)
// ---------------------------------------------------------------------------
__device__ float g_xw[(size_t)B_ * T_ * G4];          // [B*T, 4H] input proj
__device__ __nv_bfloat16 g_uthi[(size_t)G4 * H_];     // U^T hi [4096][1024]
__device__ __nv_bfloat16 g_utlo[(size_t)G4 * H_];     // U^T lo
__device__ __nv_bfloat16 g_wthi[(size_t)G4 * D_];     // W^T hi [4096][512]
__device__ __nv_bfloat16 g_wtlo[(size_t)G4 * D_];     // W^T lo
__device__ __nv_bfloat16 g_xhi[(size_t)B_ * T_ * D_]; // x hi [32768][512]
__device__ __nv_bfloat16 g_xlo[(size_t)B_ * T_ * D_]; // x lo
__device__ __nv_bfloat16 g_hh[2][B_ * H_];            // h hi, ping-pong by t
__device__ __nv_bfloat16 g_hl[2][B_ * H_];            // h lo, ping-pong by t
__device__ float g_c[B_ * H_];                        // cell state
__device__ float g_part[4][64][B_ * 64];              // split-K partials
__device__ int   g_sem[64];                           // per-tile arrival sem

// ---------------------------------------------------------------------------
// PTX wrappers (proven)
// ---------------------------------------------------------------------------
__device__ __forceinline__ void ldsm4(uint32_t& r0, uint32_t& r1,
                                      uint32_t& r2, uint32_t& r3,
                                      uint32_t addr) {
    asm volatile(
        "ldmatrix.sync.aligned.m8n8.x4.shared.b16 {%0,%1,%2,%3}, [%4];"
        : "=r"(r0), "=r"(r1), "=r"(r2), "=r"(r3)
        : "r"(addr));
}

__device__ __forceinline__ void mma_bf16(float* ac, const uint32_t* a,
                                         uint32_t b0, uint32_t b1) {
    asm volatile(
        "mma.sync.aligned.m16n8k16.row.col.f32.bf16.bf16.f32 "
        "{%0,%1,%2,%3}, {%4,%5,%6,%7}, {%8,%9}, {%0,%1,%2,%3};"
        : "+f"(ac[0]), "+f"(ac[1]), "+f"(ac[2]), "+f"(ac[3])
        : "r"(a[0]), "r"(a[1]), "r"(a[2]), "r"(a[3]), "r"(b0), "r"(b1));
}

__device__ __forceinline__ float sigmoidf_(float x) {
    return 1.0f / (1.0f + expf(-x));
}

// ---------------------------------------------------------------------------
// Init: zero h0 (both ping-pong buffers, both splits), c0, semaphores.
// ---------------------------------------------------------------------------
__global__ void init_state_kernel() {
    int i = blockIdx.x * blockDim.x + threadIdx.x;
    if (i < B_ * H_) {
        __nv_bfloat16 z = __float2bfloat16(0.0f);
        g_hh[0][i] = z; g_hh[1][i] = z;
        g_hl[0][i] = z; g_hl[1][i] = z;
        g_c[i] = 0.0f;
    }
    if (i < 64) g_sem[i] = 0;
}

// ---------------------------------------------------------------------------
// Transpose + bf16 hi/lo split for U: [1024][4096] -> U^T [4096][1024]
// ---------------------------------------------------------------------------
__global__ __launch_bounds__(256) void split_u_kernel(const float* __restrict__ U) {
    __shared__ float tile[32][33];
    const int k0 = blockIdx.x * 32;
    const int n0 = blockIdx.y * 32;
    const int tid = threadIdx.x;
    #pragma unroll
    for (int i = 0; i < 4; ++i) {
        int idx = tid + 256 * i;
        int kl = idx >> 5, nl = idx & 31;
        tile[kl][nl] = U[(size_t)(k0 + kl) * G4 + n0 + nl];
    }
    __syncthreads();
    #pragma unroll
    for (int i = 0; i < 4; ++i) {
        int idx = tid + 256 * i;
        int nl = idx >> 5, kl = idx & 31;
        float v = tile[kl][nl];
        __nv_bfloat16 hi = __float2bfloat16(v);
        __nv_bfloat16 lo = __float2bfloat16(v - __bfloat162float(hi));
        size_t dst = (size_t)(n0 + nl) * H_ + k0 + kl;
        g_uthi[dst] = hi;
        g_utlo[dst] = lo;
    }
}

// ---------------------------------------------------------------------------
// Same for W: [512][4096] -> W^T [4096][512]
// ---------------------------------------------------------------------------
__global__ __launch_bounds__(256) void split_w_kernel(const float* __restrict__ W) {
    __shared__ float tile[32][33];
    const int k0 = blockIdx.x * 32;
    const int n0 = blockIdx.y * 32;
    const int tid = threadIdx.x;
    #pragma unroll
    for (int i = 0; i < 4; ++i) {
        int idx = tid + 256 * i;
        int kl = idx >> 5, nl = idx & 31;
        tile[kl][nl] = W[(size_t)(k0 + kl) * G4 + n0 + nl];
    }
    __syncthreads();
    #pragma unroll
    for (int i = 0; i < 4; ++i) {
        int idx = tid + 256 * i;
        int nl = idx >> 5, kl = idx & 31;
        float v = tile[kl][nl];
        __nv_bfloat16 hi = __float2bfloat16(v);
        __nv_bfloat16 lo = __float2bfloat16(v - __bfloat162float(hi));
        size_t dst = (size_t)(n0 + nl) * D_ + k0 + kl;
        g_wthi[dst] = hi;
        g_wtlo[dst] = lo;
    }
}

// ---------------------------------------------------------------------------
// Elementwise bf16 hi/lo split of x, vectorized (float4 reads)
// ---------------------------------------------------------------------------
__global__ __launch_bounds__(256) void split_x_kernel(
        const float* __restrict__ x, int n4) {
    int i = blockIdx.x * blockDim.x + threadIdx.x;
    if (i < n4) {
        float4 v = reinterpret_cast<const float4*>(x)[i];
        __nv_bfloat16 h0 = __float2bfloat16(v.x);
        __nv_bfloat16 h1 = __float2bfloat16(v.y);
        __nv_bfloat16 h2 = __float2bfloat16(v.z);
        __nv_bfloat16 h3 = __float2bfloat16(v.w);
        __nv_bfloat162 hi01; hi01.x = h0; hi01.y = h1;
        __nv_bfloat162 hi23; hi23.x = h2; hi23.y = h3;
        __nv_bfloat162 lo01;
        lo01.x = __float2bfloat16(v.x - __bfloat162float(h0));
        lo01.y = __float2bfloat16(v.y - __bfloat162float(h1));
        __nv_bfloat162 lo23;
        lo23.x = __float2bfloat16(v.z - __bfloat162float(h2));
        lo23.y = __float2bfloat16(v.w - __bfloat162float(h3));
        *reinterpret_cast<__nv_bfloat162*>(&g_xhi[i * 4]) = hi01;
        *reinterpret_cast<__nv_bfloat162*>(&g_xhi[i * 4 + 2]) = hi23;
        *reinterpret_cast<__nv_bfloat162*>(&g_xlo[i * 4]) = lo01;
        *reinterpret_cast<__nv_bfloat162*>(&g_xlo[i * 4 + 2]) = lo23;
    }
}

// ---------------------------------------------------------------------------
// Phase 1 on tensor cores (ROUND-12 VERBATIM — proven, no spill).
// ---------------------------------------------------------------------------
#define G1_STR 72
__global__ __launch_bounds__(256) void gemm1_mma_kernel(
        const float* __restrict__ bias) {
    __shared__ __align__(16) __nv_bfloat16 Ahs[64][G1_STR];
    __shared__ __align__(16) __nv_bfloat16 Als[64][G1_STR];
    __shared__ __align__(16) __nv_bfloat16 Bhs[64][G1_STR];
    __shared__ __align__(16) __nv_bfloat16 Bls[64][G1_STR];

    const int tid = threadIdx.x;
    const int bn = blockIdx.x * 64;
    const int bm = blockIdx.y * 64;

    const __nv_bfloat16* xh = g_xhi + (size_t)bm * D_;
    const __nv_bfloat16* xl = g_xlo + (size_t)bm * D_;
    const __nv_bfloat16* wh = g_wthi + (size_t)bn * D_;
    const __nv_bfloat16* wl = g_wtlo + (size_t)bn * D_;

    const int wid = tid >> 5, lane = tid & 31;
    const int m0 = (wid >> 1) * 16;
    const int nwb = (wid & 1) * 32;
    const int gid = lane >> 2, tig = lane & 3;

    const int rowA = m0 + (lane & 15);
    const int kofsA = (lane >> 4) * 8;
    const uint32_t aAh = (uint32_t)__cvta_generic_to_shared(&Ahs[0][0])
        + (uint32_t)(rowA * G1_STR + kofsA) * 2u;
    const uint32_t aAl = (uint32_t)__cvta_generic_to_shared(&Als[0][0])
        + (uint32_t)(rowA * G1_STR + kofsA) * 2u;

    const int rowBb = (lane & 7) + ((lane >> 4) << 3);
    const int kofsB = ((lane >> 3) & 1) * 8;
    const uint32_t aBh0 = (uint32_t)__cvta_generic_to_shared(&Bhs[0][0])
        + (uint32_t)((nwb + rowBb) * G1_STR + kofsB) * 2u;
    const uint32_t aBh1 = aBh0 + 16u * G1_STR * 2u;
    const uint32_t aBl0 = (uint32_t)__cvta_generic_to_shared(&Bls[0][0])
        + (uint32_t)((nwb + rowBb) * G1_STR + kofsB) * 2u;
    const uint32_t aBl1 = aBl0 + 16u * G1_STR * 2u;

    float acc[4][4] = {};

    for (int kc = 0; kc < 8; ++kc) {
        const int k0 = kc * 64;
        #pragma unroll
        for (int i = 0; i < 2; ++i) {
            int slot = tid + 256 * i;
            int row = slot >> 3, j = slot & 7;
            *reinterpret_cast<uint4*>(&Ahs[row][j * 8]) =
                *reinterpret_cast<const uint4*>(&xh[(size_t)row * D_ + k0 + j * 8]);
            *reinterpret_cast<uint4*>(&Als[row][j * 8]) =
                *reinterpret_cast<const uint4*>(&xl[(size_t)row * D_ + k0 + j * 8]);
            *reinterpret_cast<uint4*>(&Bhs[row][j * 8]) =
                *reinterpret_cast<const uint4*>(&wh[(size_t)row * D_ + k0 + j * 8]);
            *reinterpret_cast<uint4*>(&Bls[row][j * 8]) =
                *reinterpret_cast<const uint4*>(&wl[(size_t)row * D_ + k0 + j * 8]);
        }
        __syncthreads();
        #pragma unroll
        for (int s = 0; s < 4; ++s) {
            const uint32_t kk = (uint32_t)(s * 16) * 2u;
            {   // hi * hi
                uint32_t a[4], b0[4], b1[4];
                ldsm4(a[0], a[1], a[2], a[3], aAh + kk);
                ldsm4(b0[0], b0[1], b0[2], b0[3], aBh0 + kk);
                ldsm4(b1[0], b1[1], b1[2], b1[3], aBh1 + kk);
                mma_bf16(acc[0], a, b0[0], b0[1]);
                mma_bf16(acc[1], a, b0[2], b0[3]);
                mma_bf16(acc[2], a, b1[0], b1[1]);
                mma_bf16(acc[3], a, b1[2], b1[3]);
            }
            {   // hi * lo
                uint32_t a[4], b0[4], b1[4];
                ldsm4(a[0], a[1], a[2], a[3], aAh + kk);
                ldsm4(b0[0], b0[1], b0[2], b0[3], aBl0 + kk);
                ldsm4(b1[0], b1[1], b1[2], b1[3], aBl1 + kk);
                mma_bf16(acc[0], a, b0[0], b0[1]);
                mma_bf16(acc[1], a, b0[2], b0[3]);
                mma_bf16(acc[2], a, b1[0], b1[1]);
                mma_bf16(acc[3], a, b1[2], b1[3]);
            }
            {   // lo * hi
                uint32_t a[4], b0[4], b1[4];
                ldsm4(a[0], a[1], a[2], a[3], aAl + kk);
                ldsm4(b0[0], b0[1], b0[2], b0[3], aBh0 + kk);
                ldsm4(b1[0], b1[1], b1[2], b1[3], aBh1 + kk);
                mma_bf16(acc[0], a, b0[0], b0[1]);
                mma_bf16(acc[1], a, b0[2], b0[3]);
                mma_bf16(acc[2], a, b1[0], b1[1]);
                mma_bf16(acc[3], a, b1[2], b1[3]);
            }
        }
        __syncthreads();
    }

    #pragma unroll
    for (int nf = 0; nf < 4; ++nf) {
        int col = bn + nwb + nf * 8 + 2 * tig;
        float b0 = bias[col], b1 = bias[col + 1];
        size_t r0 = (size_t)(bm + m0 + gid) * G4 + col;
        size_t r1 = (size_t)(bm + m0 + gid + 8) * G4 + col;
        *reinterpret_cast<float2*>(&g_xw[r0]) =
            make_float2(acc[nf][0] + b0, acc[nf][1] + b1);
        *reinterpret_cast<float2*>(&g_xw[r1]) =
            make_float2(acc[nf][2] + b0, acc[nf][3] + b1);
    }
}

// ---------------------------------------------------------------------------
// Fused LSTM step, split-K 4, 2 CTAs/SM. Grid 256 = 64 tiles x 4 K-quarters.
// Synchronous per-chunk B copy (transient regs only) + __launch_bounds__(256,2)
// so 2 CTAs co-reside per SM (smem 94.7KB*2 = 185KiB fits) and hide each
// other's load/sync latency. h ping-pongs by t; last of 4 arrivers reduces
// partials + xW + pointwise.
// ---------------------------------------------------------------------------
#define KZ_ 4
#define KP_ 256                       // K per partition
#define A_STRIDE 264                  // 256 + 8 pad (bf16 elems)
#define B_STRIDE 40                   // 32 + 8 pad
#define OFF_AHI 0                     // 64*264*2 = 33792
#define OFF_ALO 33792
#define OFF_BHI 67584                 // 64*40*2 = 5120
#define OFF_BLO 72704
#define OFF_GS  77824                 // 64*66*4 = 16896
#define SMEM_P  94720

__global__ __launch_bounds__(256, 2) void lstm_step_mma(
        int t, float* __restrict__ final_out) {
    extern __shared__ char smem[];
    __nv_bfloat16* Ahi = (__nv_bfloat16*)(smem + OFF_AHI);
    __nv_bfloat16* Alo = (__nv_bfloat16*)(smem + OFF_ALO);
    __nv_bfloat16* Bhi = (__nv_bfloat16*)(smem + OFF_BHI);
    __nv_bfloat16* Blo = (__nv_bfloat16*)(smem + OFF_BLO);
    float* Gsf = (float*)(smem + OFF_GS);
    __shared__ int s_old;

    const int tid = threadIdx.x;
    const int tile = blockIdx.x >> 2;        // 0..63 column tile
    const int kz = blockIdx.x & 3;           // K quarter
    const int n0 = tile * 16;                // hidden-unit base

    const __nv_bfloat16* hin_h = g_hh[t & 1] + kz * KP_;
    const __nv_bfloat16* hin_l = g_hl[t & 1] + kz * KP_;

    // ---- Load resident A (h hi/lo, this CTA's K quarter): 64 x 256 ----
    #pragma unroll
    for (int i = 0; i < 8; ++i) {
        int slot = tid + 256 * i;            // 0..2047
        int row = slot >> 5;                 // 0..63
        int j = slot & 31;                   // 8-elem k-group
        *reinterpret_cast<uint4*>(&Ahi[row * A_STRIDE + j * 8]) =
            *reinterpret_cast<const uint4*>(&hin_h[row * H_ + j * 8]);
        *reinterpret_cast<uint4*>(&Alo[row * A_STRIDE + j * 8]) =
            *reinterpret_cast<const uint4*>(&hin_l[row * H_ + j * 8]);
    }

    // ---- B source pointers: thread -> (gate-col cc, 16B k-group kg) ----
    const int cc = tid >> 2;                 // 0..63
    const int kg = tid & 3;                  // 0..3
    const int colg = (cc >> 4) * H_ + n0 + (cc & 15);
    const __nv_bfloat16* ubh = g_uthi + (size_t)colg * H_ + kz * KP_;
    const __nv_bfloat16* ubl = g_utlo + (size_t)colg * H_ + kz * KP_;

    // ---- Warp / fragment addressing ----
    const int wid = tid >> 5, lane = tid & 31;
    const int m0 = (wid >> 1) * 16;
    const int nwb = (wid & 1) * 32;
    const int gid = lane >> 2, tig = lane & 3;

    const int rowA = m0 + (lane & 15);
    const int kofsA = (lane >> 4) * 8;
    const uint32_t aAhi = (uint32_t)__cvta_generic_to_shared(Ahi)
                          + (uint32_t)(rowA * A_STRIDE + kofsA) * 2u;
    const uint32_t aAlo = (uint32_t)__cvta_generic_to_shared(Alo)
                          + (uint32_t)(rowA * A_STRIDE + kofsA) * 2u;

    const int rowBb = (lane & 7) + ((lane >> 4) << 3);
    const int kofsB = ((lane >> 3) & 1) * 8;
    const uint32_t aBhi0 = (uint32_t)__cvta_generic_to_shared(Bhi)
                           + (uint32_t)((nwb + rowBb) * B_STRIDE + kofsB) * 2u;
    const uint32_t aBhi1 = aBhi0 + 16u * B_STRIDE * 2u;
    const uint32_t aBlo0 = (uint32_t)__cvta_generic_to_shared(Blo)
                           + (uint32_t)((nwb + rowBb) * B_STRIDE + kofsB) * 2u;
    const uint32_t aBlo1 = aBlo0 + 16u * B_STRIDE * 2u;

    float acc[4][4] = {};

    // ---- Main loop: 8 B-tiles of BK=32, SYNCHRONOUS copy per tile ----
    for (int kt = 0; kt < 8; ++kt) {
        *reinterpret_cast<uint4*>(&Bhi[cc * B_STRIDE + kg * 8]) =
            *reinterpret_cast<const uint4*>(&ubh[kt * 32 + kg * 8]);
        *reinterpret_cast<uint4*>(&Blo[cc * B_STRIDE + kg * 8]) =
            *reinterpret_cast<const uint4*>(&ubl[kt * 32 + kg * 8]);
        __syncthreads();
        #pragma unroll
        for (int ch = 0; ch < 2; ++ch) {
            const uint32_t kcA = (uint32_t)(kt * 32 + ch * 16) * 2u;
            const uint32_t kcB = (uint32_t)(ch * 16) * 2u;
            {   // A-hi passes (hi*hi then hi*lo)
                uint32_t a[4];
                ldsm4(a[0], a[1], a[2], a[3], aAhi + kcA);
                {
                    uint32_t b0[4], b1[4];
                    ldsm4(b0[0], b0[1], b0[2], b0[3], aBhi0 + kcB);
                    ldsm4(b1[0], b1[1], b1[2], b1[3], aBhi1 + kcB);
                    mma_bf16(acc[0], a, b0[0], b0[1]);
                    mma_bf16(acc[1], a, b0[2], b0[3]);
                    mma_bf16(acc[2], a, b1[0], b1[1]);
                    mma_bf16(acc[3], a, b1[2], b1[3]);
                }
                {
                    uint32_t b0[4], b1[4];
                    ldsm4(b0[0], b0[1], b0[2], b0[3], aBlo0 + kcB);
                    ldsm4(b1[0], b1[1], b1[2], b1[3], aBlo1 + kcB);
                    mma_bf16(acc[0], a, b0[0], b0[1]);
                    mma_bf16(acc[1], a, b0[2], b0[3]);
                    mma_bf16(acc[2], a, b1[0], b1[1]);
                    mma_bf16(acc[3], a, b1[2], b1[3]);
                }
            }
            {   // A-lo pass (lo*hi)
                uint32_t a[4], b0[4], b1[4];
                ldsm4(a[0], a[1], a[2], a[3], aAlo + kcA);
                ldsm4(b0[0], b0[1], b0[2], b0[3], aBhi0 + kcB);
                ldsm4(b1[0], b1[1], b1[2], b1[3], aBhi1 + kcB);
                mma_bf16(acc[0], a, b0[0], b0[1]);
                mma_bf16(acc[1], a, b0[2], b0[3]);
                mma_bf16(acc[2], a, b1[0], b1[1]);
                mma_bf16(acc[3], a, b1[2], b1[3]);
            }
        }
        __syncthreads();
    }

    // ---- Write this K-quarter's partials ----
    float* mypart = &g_part[kz][tile][0];
    #pragma unroll
    for (int nf = 0; nf < 4; ++nf) {
        int col = nwb + nf * 8 + 2 * tig;
        *reinterpret_cast<float2*>(&mypart[(m0 + gid) * 64 + col]) =
            make_float2(acc[nf][0], acc[nf][1]);
        *reinterpret_cast<float2*>(&mypart[(m0 + gid + 8) * 64 + col]) =
            make_float2(acc[nf][2], acc[nf][3]);
    }
    __threadfence();
    __syncthreads();
    if (tid == 0) s_old = atomicAdd(&g_sem[tile], 1);
    __syncthreads();
    if (s_old != KZ_ * t + (KZ_ - 1)) return;   // not the last arriver
    __threadfence();

    // ---- Last arriver: sum all 4 partials into Gs (fixed order) ----
    #pragma unroll
    for (int nf = 0; nf < 4; ++nf) {
        int col = nwb + nf * 8 + 2 * tig;
        int r0 = (m0 + gid) * 64 + col;
        int r1 = (m0 + gid + 8) * 64 + col;
        float2 s0 = make_float2(0.0f, 0.0f);
        float2 s1 = make_float2(0.0f, 0.0f);
        #pragma unroll
        for (int z = 0; z < KZ_; ++z) {
            float2 a = *reinterpret_cast<const float2*>(&g_part[z][tile][r0]);
            float2 b = *reinterpret_cast<const float2*>(&g_part[z][tile][r1]);
            s0.x += a.x; s0.y += a.y;
            s1.x += b.x; s1.y += b.y;
        }
        *reinterpret_cast<float2*>(&Gsf[(m0 + gid) * 66 + col]) = s0;
        *reinterpret_cast<float2*>(&Gsf[(m0 + gid + 8) * 66 + col]) = s1;
    }
    __syncthreads();

    // ---- Fused pointwise: 1024 (b, off) pairs / 256 threads = 4 each ----
    __nv_bfloat16* hout_h = g_hh[(t + 1) & 1];
    __nv_bfloat16* hout_l = g_hl[(t + 1) & 1];
    const bool last = (t == T_ - 1);
    #pragma unroll
    for (int i = 0; i < 4; ++i) {
        int p = tid + 256 * i;               // 0..1023
        int b = p >> 4;
        int off = p & 15;
        const float* xwrow = &g_xw[((size_t)b * T_ + t) * G4 + n0 + off];
        float gi = Gsf[b * 66 + 0 * 16 + off] + xwrow[0 * H_];
        float gf = Gsf[b * 66 + 1 * 16 + off] + xwrow[1 * H_];
        float gc = Gsf[b * 66 + 2 * 16 + off] + xwrow[2 * H_];
        float go = Gsf[b * 66 + 3 * 16 + off] + xwrow[3 * H_];
        float iv = sigmoidf_(gi);
        float fv = sigmoidf_(gf);
        float cb = tanhf(gc);
        float ov = sigmoidf_(go);
        int idx = b * H_ + n0 + off;
        float cn = fv * g_c[idx] + iv * cb;
        g_c[idx] = cn;
        float hn = ov * tanhf(cn);
        __nv_bfloat16 hb = __float2bfloat16(hn);
        hout_h[idx] = hb;
        hout_l[idx] = __float2bfloat16(hn - __bfloat162float(hb));
        if (last) final_out[idx] = hn;
    }
}

// ---------------------------------------------------------------------------
// Launch: init -> splits -> tensor-core phase-1 -> 512 split-K-4 step kernels
// ---------------------------------------------------------------------------
extern "C" void kernel_launch(void* const* d_in, const int* in_sizes, int n_in,
                              void* d_out, int out_size) {
    const float* x = (const float*)d_in[0];
    const float* W = (const float*)d_in[1];
    const float* U = (const float*)d_in[2];
    const float* b = (const float*)d_in[3];
    float* out = (float*)d_out;

    cudaFuncSetAttribute(lstm_step_mma,
                         cudaFuncAttributeMaxDynamicSharedMemorySize, SMEM_P);

    init_state_kernel<<<(B_ * H_ + 255) / 256, 256>>>();

    dim3 gu(H_ / 32, G4 / 32);               // (32, 128)
    split_u_kernel<<<gu, 256>>>(U);
    dim3 gw(D_ / 32, G4 / 32);               // (16, 128)
    split_w_kernel<<<gw, 256>>>(W);

    int n4 = (B_ * T_ * D_) / 4;
    split_x_kernel<<<(n4 + 255) / 256, 256>>>(x, n4);

    dim3 g1(G4 / 64, (B_ * T_) / 64);        // (64, 512)
    gemm1_mma_kernel<<<g1, 256>>>(b);

    for (int t = 0; t < T_; ++t) {
        lstm_step_mma<<<64 * KZ_, 256, SMEM_P>>>(t, out);
    }
}